// round 14
// baseline (speedup 1.0000x reference)
#include <cuda_runtime.h>
#include <cuda_bf16.h>
#include <cstdint>
#include <cstddef>

// Problem constants
#define B_  4
#define S_  2048
#define D_  1024
#define M_  (B_ * S_)     // 8192
#define K2_ (2 * D_)      // 2048

// ---------------------------------------------------------------------------
// Scratch (static __device__ — no allocations allowed)
// ---------------------------------------------------------------------------
__device__ __nv_bfloat16 g_Xh [(size_t)M_  * K2_];   // z-cat hi
__device__ __nv_bfloat16 g_Xl [(size_t)M_  * K2_];
__device__ __nv_bfloat16 g_Zsh[(size_t)M_  * D_];    // zr+zi hi/lo
__device__ __nv_bfloat16 g_Zsl[(size_t)M_  * D_];
__device__ __nv_bfloat16 g_WqTh[(size_t)K2_ * K2_];
__device__ __nv_bfloat16 g_WqTl[(size_t)K2_ * K2_];
__device__ __nv_bfloat16 g_WkTh[(size_t)K2_ * K2_];
__device__ __nv_bfloat16 g_WkTl[(size_t)K2_ * K2_];
__device__ __nv_bfloat16 g_Gh [(size_t)K2_ * D_];    // G~ left half: Gr rows 0:1024, Gi rows 1024:2048 (ld=D)
__device__ __nv_bfloat16 g_Gl [(size_t)K2_ * D_];
__device__ __nv_bfloat16 g_Gsh[(size_t)D_ * D_];     // Gr+Gi
__device__ __nv_bfloat16 g_Gsl[(size_t)D_ * D_];
__device__ __nv_bfloat16 g_Evrh[(size_t)D_ * D_];    // wv_r split
__device__ __nv_bfloat16 g_Evrl[(size_t)D_ * D_];
__device__ __nv_bfloat16 g_Evih[(size_t)D_ * D_];    // wv_i split
__device__ __nv_bfloat16 g_Evil[(size_t)D_ * D_];
__device__ __nv_bfloat16 g_Evsh[(size_t)D_ * D_];    // wv_r+wv_i split
__device__ __nv_bfloat16 g_Evsl[(size_t)D_ * D_];
__device__ float g_M1u[(size_t)M_ * D_];             // Karatsuba fp32 scratch (also G k-split partials)
__device__ float g_M2u[(size_t)M_ * D_];
__device__ float g_M1v[(size_t)M_ * D_];
__device__ float g_M2v[(size_t)M_ * D_];
__device__ __nv_bfloat16 g_Uh [(size_t)M_  * K2_];   // U concat [Ur|Ui]
__device__ __nv_bfloat16 g_Ul [(size_t)M_  * K2_];
__device__ __nv_bfloat16 g_Vh [(size_t)M_  * K2_];   // V concat [Vr|Vi] (row-major)
__device__ __nv_bfloat16 g_Vl [(size_t)M_  * K2_];
__device__ __nv_bfloat16 g_Vth[(size_t)B_ * K2_ * S_]; // V transposed [b][d'][t]
__device__ __nv_bfloat16 g_Vtl[(size_t)B_ * K2_ * S_];
__device__ float         g_P  [(size_t)B_ * S_ * S_];
__device__ __nv_bfloat16 g_Ph [(size_t)B_ * S_ * S_];
__device__ __nv_bfloat16 g_Pl [(size_t)B_ * S_ * S_];

// ---------------------------------------------------------------------------
// PTX helpers (sm_80-era only — NO tcgen05: harness targets plain sm_103)
// ---------------------------------------------------------------------------
__device__ __forceinline__ uint32_t smem_u32(const void* p) {
    uint32_t a;
    asm("{ .reg .u64 t; cvta.to.shared.u64 t, %1; cvt.u32.u64 %0, t; }" : "=r"(a) : "l"(p));
    return a;
}
__device__ __forceinline__ void cp16(uint32_t saddr, const void* gaddr) {
    asm volatile("cp.async.cg.shared.global [%0], [%1], 16;" :: "r"(saddr), "l"(gaddr));
}
#define CP_COMMIT() asm volatile("cp.async.commit_group;" ::: "memory")
#define CP_WAIT0()  asm volatile("cp.async.wait_group 0;" ::: "memory")

__device__ __forceinline__ void ldsm_x4(uint32_t (&r)[4], uint32_t addr) {
    asm volatile("ldmatrix.sync.aligned.m8n8.x4.shared.b16 {%0,%1,%2,%3}, [%4];"
        : "=r"(r[0]), "=r"(r[1]), "=r"(r[2]), "=r"(r[3]) : "r"(addr));
}
__device__ __forceinline__ void mma16816(float (&c)[4], const uint32_t (&a)[4],
                                         const uint32_t* b) {
    asm volatile(
        "mma.sync.aligned.m16n8k16.row.col.f32.bf16.bf16.f32 "
        "{%0,%1,%2,%3}, {%4,%5,%6,%7}, {%8,%9}, {%0,%1,%2,%3};"
        : "+f"(c[0]), "+f"(c[1]), "+f"(c[2]), "+f"(c[3])
        : "r"(a[0]), "r"(a[1]), "r"(a[2]), "r"(a[3]), "r"(b[0]), "r"(b[1]));
}

// ---------------------------------------------------------------------------
// SMEM tiles: BM=128, BN=256, BK=64. Row stride 144B -> bank-group of chunk
// (r,c) = (r+c) mod 8 -> conflict-free ldmatrix, no swizzle needed.
// ---------------------------------------------------------------------------
#define ROWB 144u
#define TILE_A (128u * ROWB)          // 18432
#define TILE_Bt (256u * ROWB)         // 36864
#define OFF_AH 0u
#define OFF_AL TILE_A
#define OFF_BH (2u * TILE_A)
#define OFF_BL (2u * TILE_A + TILE_Bt)
#define BUF_STRIDE (2u * TILE_A + 2u * TILE_Bt)  // 110592
#define SMEM_G (2 * 110592)                      // 221184

#define NTHREADS 512

__device__ __forceinline__ void load_partA(uint32_t sbase, const __nv_bfloat16* __restrict__ g,
                                           int ld, int k0) {
    const int t = threadIdx.x;
    #pragma unroll
    for (int i = 0; i < 2; i++) {
        int u = t + i * NTHREADS;
        int row = u >> 3, c = u & 7;
        cp16(sbase + (uint32_t)row * ROWB + (uint32_t)c * 16,
             g + (size_t)row * ld + k0 + c * 8);
    }
}
__device__ __forceinline__ void load_partB(uint32_t sbase, const __nv_bfloat16* __restrict__ g,
                                           int ld, int k0) {
    const int t = threadIdx.x;
    #pragma unroll
    for (int i = 0; i < 4; i++) {
        int u = t + i * NTHREADS;
        int row = u >> 3, c = u & 7;
        cp16(sbase + (uint32_t)row * ROWB + (uint32_t)c * 16,
             g + (size_t)row * ld + k0 + c * 8);
    }
}
__device__ __forceinline__ void load_chunk(uint32_t buf,
    const __nv_bfloat16* Ah, const __nv_bfloat16* Al, int lda,
    const __nv_bfloat16* Bh, const __nv_bfloat16* Bl, int ldb, int k0) {
    load_partA(buf + OFF_AH, Ah, lda, k0);
    load_partA(buf + OFF_AL, Al, lda, k0);
    load_partB(buf + OFF_BH, Bh, ldb, k0);
    load_partB(buf + OFF_BL, Bl, ldb, k0);
}

// Compute one BK=64 chunk (warp tile 64x32), 3-term split, two-phase A regs.
__device__ __forceinline__ void compute_chunk(uint32_t buf, float (&acc)[4][4][4],
                                              int m0, int n0, int lane) {
    const uint32_t aBase = buf + OFF_AH
        + (uint32_t)(m0 + (lane & 15)) * ROWB + (uint32_t)(lane >> 4) * 16u;
    const uint32_t bRow = (uint32_t)((lane & 7) + ((lane >> 4) & 1) * 8);
    const uint32_t bBase = buf + OFF_BH
        + (uint32_t)(n0 + bRow) * ROWB + (uint32_t)((lane >> 3) & 1) * 16u;
    #pragma unroll
    for (int ks = 0; ks < 4; ks++) {
        uint32_t bh[4][2], bl[4][2];
        #pragma unroll
        for (int np = 0; np < 2; np++) {
            uint32_t r[4];
            ldsm_x4(r, bBase + (uint32_t)(np * 16) * ROWB + ks * 32u);
            bh[2 * np][0] = r[0]; bh[2 * np][1] = r[1];
            bh[2 * np + 1][0] = r[2]; bh[2 * np + 1][1] = r[3];
            ldsm_x4(r, bBase + (OFF_BL - OFF_BH) + (uint32_t)(np * 16) * ROWB + ks * 32u);
            bl[2 * np][0] = r[0]; bl[2 * np][1] = r[1];
            bl[2 * np + 1][0] = r[2]; bl[2 * np + 1][1] = r[3];
        }
        {
            uint32_t a[4][4];
            #pragma unroll
            for (int mt = 0; mt < 4; mt++)
                ldsm_x4(a[mt], aBase + (uint32_t)(mt * 16) * ROWB + ks * 32u);
            #pragma unroll
            for (int mt = 0; mt < 4; mt++)
                #pragma unroll
                for (int nt = 0; nt < 4; nt++) {
                    mma16816(acc[mt][nt], a[mt], bh[nt]);   // hi*hi
                    mma16816(acc[mt][nt], a[mt], bl[nt]);   // hi*lo
                }
            #pragma unroll
            for (int mt = 0; mt < 4; mt++)
                ldsm_x4(a[mt], aBase + (OFF_AL - OFF_AH) + (uint32_t)(mt * 16) * ROWB + ks * 32u);
            #pragma unroll
            for (int mt = 0; mt < 4; mt++)
                #pragma unroll
                for (int nt = 0; nt < 4; nt++)
                    mma16816(acc[mt][nt], a[mt], bh[nt]);   // lo*hi
        }
    }
}

// Mainloop: C[128,256] += A[128,kEnd] @ B[256,kEnd]^T (split-bf16, fp32 acc)
__device__ __forceinline__ void gemm_mainloop(
    const __nv_bfloat16* Ah, const __nv_bfloat16* Al, int lda,
    const __nv_bfloat16* Bh, const __nv_bfloat16* Bl, int ldb,
    int kEnd, float (&acc)[4][4][4]) {
    extern __shared__ char smem[];
    const uint32_t sb = smem_u32(smem);
    const int lane = threadIdx.x & 31;
    const int wid  = threadIdx.x >> 5;
    const int m0 = (wid >> 3) * 64;
    const int n0 = (wid & 7) * 32;

    load_chunk(sb, Ah, Al, lda, Bh, Bl, ldb, 0);
    CP_COMMIT();
    const int nc = kEnd >> 6;
    for (int c = 0; c < nc; c++) {
        const uint32_t buf = sb + (uint32_t)(c & 1) * BUF_STRIDE;
        CP_WAIT0();
        __syncthreads();
        if (c + 1 < nc) {
            load_chunk(sb + (uint32_t)((c + 1) & 1) * BUF_STRIDE,
                       Ah, Al, lda, Bh, Bl, ldb, (c + 1) << 6);
            CP_COMMIT();
        }
        compute_chunk(buf, acc, m0, n0, lane);
    }
}

// ---------------------------------------------------------------------------
// fp32 -> bf16 hi/lo split
// ---------------------------------------------------------------------------
__device__ __forceinline__ void split_bf16(float v, __nv_bfloat16& h, __nv_bfloat16& l) {
    h = __float2bfloat16(v);
    l = __float2bfloat16(v - __bfloat162float(h));
}
__device__ __forceinline__ void store_pair(__nv_bfloat16* oh, __nv_bfloat16* ol,
                                           size_t o, float f0, float f1) {
    __nv_bfloat16 h0, l0, h1, l1;
    split_bf16(f0, h0, l0);
    split_bf16(f1, h1, l1);
    *(uint32_t*)(oh + o) = ((uint32_t)__bfloat16_as_ushort(h1) << 16) | __bfloat16_as_ushort(h0);
    *(uint32_t*)(ol + o) = ((uint32_t)__bfloat16_as_ushort(l1) << 16) | __bfloat16_as_ushort(l0);
}

// Epilogue: raw fp32 store into [rows x D] scratch.
__device__ __forceinline__ void epi_f32_store(
    float (&acc)[4][4][4], float* __restrict__ o, int bm, int bn) {
    const int lane = threadIdx.x & 31, wid = threadIdx.x >> 5;
    const int m0 = bm + (wid >> 3) * 64, n0 = bn + (wid & 7) * 32;
    const int g = lane >> 2, tig = lane & 3;
    #pragma unroll
    for (int mt = 0; mt < 4; mt++)
        #pragma unroll
        for (int nt = 0; nt < 4; nt++)
            #pragma unroll
            for (int h = 0; h < 2; h++) {
                int row = m0 + mt * 16 + g + h * 8;
                int col = n0 + nt * 8 + tig * 2;
                *(float2*)(o + (size_t)row * D_ + col) =
                    make_float2(acc[mt][nt][2 * h], acc[mt][nt][2 * h + 1]);
            }
}

// ---------------------------------------------------------------------------
// pack kernels
// ---------------------------------------------------------------------------
__global__ void pack_xz(const float* __restrict__ zr, const float* __restrict__ zi) {
    int idx = blockIdx.x * 256 + threadIdx.x;       // < M_*D_
    int m = idx >> 10, k = idx & 1023;
    float vr = zr[idx], vi = zi[idx];
    size_t o = (size_t)m * K2_ + k;
    split_bf16(vr, g_Xh[o], g_Xl[o]);
    split_bf16(vi, g_Xh[o + D_], g_Xl[o + D_]);
    split_bf16(vr + vi, g_Zsh[idx], g_Zsl[idx]);
}
__global__ void pack_wT(const float* __restrict__ wqr, const float* __restrict__ wqi,
                        const float* __restrict__ wkr, const float* __restrict__ wki) {
    const int which = blockIdx.z;
    const float* wr = which ? wkr : wqr;
    const float* wi = which ? wki : wqi;
    __nv_bfloat16* oh = which ? g_WkTh : g_WqTh;
    __nv_bfloat16* ol = which ? g_WkTl : g_WqTl;
    const int i0 = blockIdx.x * 32, l0 = blockIdx.y * 32;
    const bool qi = i0 >= 1024, ql = l0 >= 1024;
    const float* src = (qi == ql) ? wr : wi;
    const float sign = (qi && !ql) ? -1.f : 1.f;
    const int r0 = l0 - (ql ? 1024 : 0), c0 = i0 - (qi ? 1024 : 0);
    __shared__ float t[32][33];
    const int tx = threadIdx.x, ty = threadIdx.y;
    #pragma unroll
    for (int j = 0; j < 32; j += 8)
        t[ty + j][tx] = src[(size_t)(r0 + ty + j) * 1024 + c0 + tx];
    __syncthreads();
    #pragma unroll
    for (int j = 0; j < 32; j += 8) {
        float v = sign * t[tx][ty + j];
        __nv_bfloat16 h, l;
        split_bf16(v, h, l);
        size_t o = (size_t)(i0 + ty + j) * K2_ + l0 + tx;
        oh[o] = h; ol[o] = l;
    }
}
__global__ void pack_ev(const float* __restrict__ wvr, const float* __restrict__ wvi) {
    int idx = blockIdx.x * 256 + threadIdx.x;       // < D_*D_
    float vr = wvr[idx], vi = wvi[idx];
    split_bf16(vr,      g_Evrh[idx], g_Evrl[idx]);
    split_bf16(vi,      g_Evih[idx], g_Evil[idx]);
    split_bf16(vr + vi, g_Evsh[idx], g_Evsl[idx]);
}

// ---------------------------------------------------------------------------
// Fused launch 1: G k-split partials (blocks 0..127) + V-Karatsuba M1/M2
// (blocks 128..639). No inter-dependency. 640 CTAs = 4.3 waves.
// ---------------------------------------------------------------------------
__global__ void __launch_bounds__(NTHREADS) k_gemm_GV() {
    float acc[4][4][4] = {};
    const int bid = blockIdx.x;
    if (bid < 128) {
        // G partial: kh = bid>>6, rem 0..63 -> bm=(rem>>2)*128, bn=(rem&3)*256
        const int kh = bid >> 6, rem = bid & 63;
        const int bm = (rem >> 2) * 128, bn = (rem & 3) * 256;
        const int koff = kh * 1024;
        gemm_mainloop(g_WqTh + (size_t)bm * K2_ + koff, g_WqTl + (size_t)bm * K2_ + koff, K2_,
                      g_WkTh + (size_t)bn * K2_ + koff, g_WkTl + (size_t)bn * K2_ + koff, K2_,
                      1024, acc);
        epi_f32_store(acc, kh ? g_M2u : g_M1u, bm, bn);
    } else {
        // V-M1 (q=0: Zr x Er) / V-M2 (q=1: Zi x Ei)
        const int v = bid - 128;
        const int q = v >> 8, rem = v & 255;
        const int bn = (rem & 3) * 256, bm = (rem >> 2) * 128;
        const int aoff = q ? D_ : 0;
        const __nv_bfloat16* Bh = q ? g_Evih : g_Evrh;
        const __nv_bfloat16* Bl = q ? g_Evil : g_Evrl;
        gemm_mainloop(g_Xh + (size_t)bm * K2_ + aoff, g_Xl + (size_t)bm * K2_ + aoff, K2_,
                      Bh + (size_t)bn * D_, Bl + (size_t)bn * D_, D_, D_, acc);
        epi_f32_store(acc, q ? g_M2v : g_M1v, bm, bn);
    }
}

// Reduce G partials -> Gh/Gl (both Gr and Gi rows) + Gs = Gr+Gi.  grid(4096)
__global__ void reduce_G() {
    int idx = blockIdx.x * 256 + threadIdx.x;       // < D_*D_ (Gr element)
    const size_t DD = (size_t)D_ * D_;
    float gr = g_M1u[idx] + g_M2u[idx];
    float gi = g_M1u[idx + DD] + g_M2u[idx + DD];
    split_bf16(gr, g_Gh[idx], g_Gl[idx]);
    split_bf16(gi, g_Gh[idx + DD], g_Gl[idx + DD]);
    split_bf16(gr + gi, g_Gsh[idx], g_Gsl[idx]);
}

// ---------------------------------------------------------------------------
// U-Karatsuba M1/M2.  grid(8, 64): quad 0 = Zr x Gr -> M1u, 1 = Zi x Gi -> M2u
// ---------------------------------------------------------------------------
__global__ void __launch_bounds__(NTHREADS) k_gemm_M12U() {
    float acc[4][4][4] = {};
    const int quad = blockIdx.x >> 2;
    const int bn = (blockIdx.x & 3) * 256;
    const int bm = blockIdx.y * 128;
    const int aoff = quad ? D_ : 0;
    const __nv_bfloat16* Bh = g_Gh + (quad ? (size_t)D_ * D_ : 0);
    const __nv_bfloat16* Bl = g_Gl + (quad ? (size_t)D_ * D_ : 0);
    gemm_mainloop(g_Xh + (size_t)bm * K2_ + aoff, g_Xl + (size_t)bm * K2_ + aoff, K2_,
                  Bh + (size_t)bn * D_, Bl + (size_t)bn * D_, D_, D_, acc);
    epi_f32_store(acc, quad ? g_M2u : g_M1u, bm, bn);
}

// ---------------------------------------------------------------------------
// Karatsuba M3 + closer.  grid(8, 64)
// half 0: U-M3 = Zs x Gs -> U = [M1-M2 | M3-M1-M2]
// half 1: V-M3 = Zs x Es -> V = [M1-M2 | M3-M1-M2]  (row-major; vtrans follows)
// ---------------------------------------------------------------------------
__global__ void __launch_bounds__(NTHREADS) k_gemm_M3() {
    float acc[4][4][4] = {};
    const int half = blockIdx.x >> 2;
    const int bn = (blockIdx.x & 3) * 256;
    const int bm = blockIdx.y * 128;
    const __nv_bfloat16* Bh = half ? g_Evsh : g_Gsh;
    const __nv_bfloat16* Bl = half ? g_Evsl : g_Gsl;
    gemm_mainloop(g_Zsh + (size_t)bm * D_, g_Zsl + (size_t)bm * D_, D_,
                  Bh + (size_t)bn * D_, Bl + (size_t)bn * D_, D_, D_, acc);
    const float* M1 = half ? g_M1v : g_M1u;
    const float* M2 = half ? g_M2v : g_M2u;
    __nv_bfloat16* oh = half ? g_Vh : g_Uh;
    __nv_bfloat16* ol = half ? g_Vl : g_Ul;
    const int lane = threadIdx.x & 31, wid = threadIdx.x >> 5;
    const int m0 = bm + (wid >> 3) * 64, n0 = bn + (wid & 7) * 32;
    const int g = lane >> 2, tig = lane & 3;
    #pragma unroll
    for (int mt = 0; mt < 4; mt++)
        #pragma unroll
        for (int nt = 0; nt < 4; nt++)
            #pragma unroll
            for (int h = 0; h < 2; h++) {
                int row = m0 + mt * 16 + g + h * 8;
                int col = n0 + nt * 8 + tig * 2;
                float2 m1 = *(const float2*)(M1 + (size_t)row * D_ + col);
                float2 m2 = *(const float2*)(M2 + (size_t)row * D_ + col);
                float a0 = acc[mt][nt][2 * h], a1 = acc[mt][nt][2 * h + 1];
                store_pair(oh, ol, (size_t)row * K2_ + col, m1.x - m2.x, m1.y - m2.y);
                store_pair(oh, ol, (size_t)row * K2_ + D_ + col,
                           a0 - m1.x - m2.x, a1 - m1.y - m2.y);
            }
}

// ---------------------------------------------------------------------------
// Transpose V~ -> Vt (hi, lo)   grid(64, 64, 4), block(32, 8)
// ---------------------------------------------------------------------------
__global__ void vtrans() {
    __shared__ __nv_bfloat16 th[32][33], tl[32][33];
    const int b = blockIdx.z, d0 = blockIdx.x * 32, t0 = blockIdx.y * 32;
    const int tx = threadIdx.x, ty = threadIdx.y;
    #pragma unroll
    for (int j = 0; j < 32; j += 8) {
        size_t src = ((size_t)(b * S_ + t0 + ty + j)) * K2_ + d0 + tx;
        th[ty + j][tx] = g_Vh[src];
        tl[ty + j][tx] = g_Vl[src];
    }
    __syncthreads();
    #pragma unroll
    for (int j = 0; j < 32; j += 8) {
        size_t dst = ((size_t)b * K2_ + d0 + ty + j) * S_ + t0 + tx;
        g_Vth[dst] = th[tx][ty + j];
        g_Vtl[dst] = tl[tx][ty + j];
    }
}

// ---------------------------------------------------------------------------
// GEMM scores: scores = Z~ @ U^T, causal tile skip   grid(8,16,4)
// ---------------------------------------------------------------------------
__global__ void __launch_bounds__(NTHREADS) k_gemm_scores() {
    if ((int)blockIdx.x * 2 > (int)blockIdx.y) return;
    float acc[4][4][4] = {};
    const int b = blockIdx.z, bm = blockIdx.y * 128, bn = blockIdx.x * 256;
    gemm_mainloop(g_Xh + ((size_t)(b * S_ + bm)) * K2_,
                  g_Xl + ((size_t)(b * S_ + bm)) * K2_, K2_,
                  g_Uh + ((size_t)(b * S_ + bn)) * K2_,
                  g_Ul + ((size_t)(b * S_ + bn)) * K2_, K2_, K2_, acc);
    const int lane = threadIdx.x & 31, wid = threadIdx.x >> 5;
    const int m0 = bm + (wid >> 3) * 64, n0 = bn + (wid & 7) * 32;
    const int g = lane >> 2, tig = lane & 3;
    float* C = g_P + (size_t)b * S_ * S_;
    #pragma unroll
    for (int mt = 0; mt < 4; mt++)
        #pragma unroll
        for (int nt = 0; nt < 4; nt++)
            #pragma unroll
            for (int h = 0; h < 2; h++) {
                int row = m0 + mt * 16 + g + h * 8;
                int col = n0 + nt * 8 + tig * 2;
                *(float2*)(C + (size_t)row * S_ + col) =
                    make_float2(acc[mt][nt][2 * h], acc[mt][nt][2 * h + 1]);
            }
}

// ---------------------------------------------------------------------------
// Causal softmax: g_P -> g_Ph/g_Pl (bf16 hi/lo, zero-padded to 128 boundary)
// ---------------------------------------------------------------------------
__global__ void __launch_bounds__(256) softmax_k() {
    const int b = blockIdx.y, s = blockIdx.x;
    const float* row = g_P + ((size_t)(b * S_ + s)) * S_;
    __nv_bfloat16* oh = g_Ph + ((size_t)(b * S_ + s)) * S_;
    __nv_bfloat16* ol = g_Pl + ((size_t)(b * S_ + s)) * S_;
    const int n = s + 1;
    const int lim = ((s >> 7) + 1) << 7;
    const float scale = 0.03125f;
    __shared__ float red[256];
    const int tid = threadIdx.x;

    float ev[8];
    float m = -3.0e38f;
    #pragma unroll
    for (int it = 0; it < 8; it++) {
        int i = tid + it * 256;
        float v = (i < n) ? row[i] : -3.0e38f;
        ev[it] = v;
        m = fmaxf(m, v);
    }
    red[tid] = m; __syncthreads();
    for (int off = 128; off > 0; off >>= 1) {
        if (tid < off) red[tid] = fmaxf(red[tid], red[tid + off]);
        __syncthreads();
    }
    const float mv = red[0] * scale;
    __syncthreads();

    float sum = 0.f;
    #pragma unroll
    for (int it = 0; it < 8; it++) {
        int i = tid + it * 256;
        float e = (i < n) ? __expf(ev[it] * scale - mv) : 0.f;
        ev[it] = e;
        sum += e;
    }
    red[tid] = sum; __syncthreads();
    for (int off = 128; off > 0; off >>= 1) {
        if (tid < off) red[tid] += red[tid + off];
        __syncthreads();
    }
    const float inv = 1.0f / red[0];

    #pragma unroll
    for (int it = 0; it < 8; it++) {
        int i = tid + it * 256;
        if (i < lim) {
            float p = (i < n) ? ev[it] * inv : 0.f;
            __nv_bfloat16 h, l;
            split_bf16(p, h, l);
            oh[i] = h; ol[i] = l;
        }
    }
}

// ---------------------------------------------------------------------------
// GEMM PV: Out = P @ Vt^T (causal K-limit), heavy tiles first  grid(8,16,4)
// ---------------------------------------------------------------------------
__global__ void __launch_bounds__(NTHREADS) k_gemm_pv(float* __restrict__ out) {
    float acc[4][4][4] = {};
    const int b = blockIdx.z;
    const int bm = (15 - (int)blockIdx.y) * 128;   // heavy-first
    const int bn = blockIdx.x * 256;
    gemm_mainloop(g_Ph + ((size_t)(b * S_ + bm)) * S_,
                  g_Pl + ((size_t)(b * S_ + bm)) * S_, S_,
                  g_Vth + ((size_t)b * K2_ + bn) * S_,
                  g_Vtl + ((size_t)b * K2_ + bn) * S_, S_,
                  bm + 128, acc);
    const int lane = threadIdx.x & 31, wid = threadIdx.x >> 5;
    const int m0 = bm + (wid >> 3) * 64, n0 = bn + (wid & 7) * 32;
    const int g = lane >> 2, tig = lane & 3;
    #pragma unroll
    for (int mt = 0; mt < 4; mt++)
        #pragma unroll
        for (int nt = 0; nt < 4; nt++)
            #pragma unroll
            for (int h = 0; h < 2; h++) {
                int s = m0 + mt * 16 + g + h * 8;
                int col = n0 + nt * 8 + tig * 2;
                int plane = col >> 10, d = col & 1023;
                *(float2*)(out + (((size_t)plane * B_ + b) * S_ + s) * (size_t)D_ + d) =
                    make_float2(acc[mt][nt][2 * h], acc[mt][nt][2 * h + 1]);
            }
}

// ---------------------------------------------------------------------------
// Launch
// ---------------------------------------------------------------------------
extern "C" void kernel_launch(void* const* d_in, const int* in_sizes, int n_in,
                              void* d_out, int out_size) {
    const float* z_real = (const float*)d_in[0];
    const float* z_imag = (const float*)d_in[1];
    const float* wq_r   = (const float*)d_in[2];
    const float* wq_i   = (const float*)d_in[3];
    const float* wk_r   = (const float*)d_in[4];
    const float* wk_i   = (const float*)d_in[5];
    const float* wv_r   = (const float*)d_in[6];
    const float* wv_i   = (const float*)d_in[7];
    float* out = (float*)d_out;

    static int attr_done = 0;
    if (!attr_done) {
        cudaFuncSetAttribute(k_gemm_GV,     cudaFuncAttributeMaxDynamicSharedMemorySize, SMEM_G);
        cudaFuncSetAttribute(k_gemm_M12U,   cudaFuncAttributeMaxDynamicSharedMemorySize, SMEM_G);
        cudaFuncSetAttribute(k_gemm_M3,     cudaFuncAttributeMaxDynamicSharedMemorySize, SMEM_G);
        cudaFuncSetAttribute(k_gemm_scores, cudaFuncAttributeMaxDynamicSharedMemorySize, SMEM_G);
        cudaFuncSetAttribute(k_gemm_pv,     cudaFuncAttributeMaxDynamicSharedMemorySize, SMEM_G);
        attr_done = 1;
    }

    pack_xz<<<(M_ * D_) / 256, 256>>>(z_real, z_imag);
    pack_wT<<<dim3(64, 64, 2), dim3(32, 8)>>>(wq_r, wq_i, wk_r, wk_i);
    pack_ev<<<(D_ * D_) / 256, 256>>>(wv_r, wv_i);
    k_gemm_GV<<<640, NTHREADS, SMEM_G>>>();
    reduce_G<<<(D_ * D_) / 256, 256>>>();
    k_gemm_M12U<<<dim3(8, M_ / 128), NTHREADS, SMEM_G>>>();
    k_gemm_M3<<<dim3(8, M_ / 128), NTHREADS, SMEM_G>>>();
    vtrans<<<dim3(K2_ / 32, S_ / 32, B_), dim3(32, 8)>>>();
    k_gemm_scores<<<dim3(S_ / 256, S_ / 128, B_), NTHREADS, SMEM_G>>>();
    softmax_k<<<dim3(S_, B_), 256>>>();
    k_gemm_pv<<<dim3(K2_ / 256, S_ / 128, B_), NTHREADS, SMEM_G>>>(out);
}

// round 16
// speedup vs baseline: 1.0588x; 1.0588x over previous
#include <cuda_runtime.h>
#include <cuda_bf16.h>
#include <cstdint>
#include <cstddef>

// Problem constants
#define B_  4
#define S_  2048
#define D_  1024
#define M_  (B_ * S_)     // 8192
#define K2_ (2 * D_)      // 2048

// ---------------------------------------------------------------------------
// Scratch (static __device__ — no allocations allowed)
// ---------------------------------------------------------------------------
__device__ __nv_bfloat16 g_Xh [(size_t)M_  * K2_];   // z-cat hi
__device__ __nv_bfloat16 g_Xl [(size_t)M_  * K2_];
__device__ __nv_bfloat16 g_Zsh[(size_t)M_  * D_];    // zr+zi hi/lo
__device__ __nv_bfloat16 g_Zsl[(size_t)M_  * D_];
__device__ __nv_bfloat16 g_WqTh[(size_t)K2_ * K2_];
__device__ __nv_bfloat16 g_WqTl[(size_t)K2_ * K2_];
__device__ __nv_bfloat16 g_WkTh[(size_t)K2_ * K2_];
__device__ __nv_bfloat16 g_WkTl[(size_t)K2_ * K2_];
__device__ __nv_bfloat16 g_Gh [(size_t)K2_ * D_];    // G~ left half: Gr rows 0:1024, Gi rows 1024:2048 (ld=D)
__device__ __nv_bfloat16 g_Gl [(size_t)K2_ * D_];
__device__ __nv_bfloat16 g_Gsh[(size_t)D_ * D_];     // Gr+Gi
__device__ __nv_bfloat16 g_Gsl[(size_t)D_ * D_];
__device__ __nv_bfloat16 g_Evrh[(size_t)D_ * D_];    // wv_r split
__device__ __nv_bfloat16 g_Evrl[(size_t)D_ * D_];
__device__ __nv_bfloat16 g_Evih[(size_t)D_ * D_];    // wv_i split
__device__ __nv_bfloat16 g_Evil[(size_t)D_ * D_];
__device__ __nv_bfloat16 g_Evsh[(size_t)D_ * D_];    // wv_r+wv_i split
__device__ __nv_bfloat16 g_Evsl[(size_t)D_ * D_];
__device__ float g_M1u[(size_t)M_ * D_];             // Karatsuba fp32 scratch (also G k-split partials)
__device__ float g_M2u[(size_t)M_ * D_];
__device__ float g_M1v[(size_t)M_ * D_];
__device__ float g_M2v[(size_t)M_ * D_];
__device__ __nv_bfloat16 g_Uh [(size_t)M_  * K2_];   // U concat [Ur|Ui]
__device__ __nv_bfloat16 g_Ul [(size_t)M_  * K2_];
__device__ __nv_bfloat16 g_Vth[(size_t)B_ * K2_ * S_]; // V transposed [b][d'][t]
__device__ __nv_bfloat16 g_Vtl[(size_t)B_ * K2_ * S_];
__device__ float         g_P  [(size_t)B_ * S_ * S_];
__device__ __nv_bfloat16 g_Ph [(size_t)B_ * S_ * S_];
__device__ __nv_bfloat16 g_Pl [(size_t)B_ * S_ * S_];

// ---------------------------------------------------------------------------
// PTX helpers (sm_80-era only — NO tcgen05: harness targets plain sm_103)
// ---------------------------------------------------------------------------
__device__ __forceinline__ uint32_t smem_u32(const void* p) {
    uint32_t a;
    asm("{ .reg .u64 t; cvta.to.shared.u64 t, %1; cvt.u32.u64 %0, t; }" : "=r"(a) : "l"(p));
    return a;
}
__device__ __forceinline__ void cp16(uint32_t saddr, const void* gaddr) {
    asm volatile("cp.async.cg.shared.global [%0], [%1], 16;" :: "r"(saddr), "l"(gaddr));
}
#define CP_COMMIT() asm volatile("cp.async.commit_group;" ::: "memory")
#define CP_WAIT0()  asm volatile("cp.async.wait_group 0;" ::: "memory")

__device__ __forceinline__ void ldsm_x4(uint32_t (&r)[4], uint32_t addr) {
    asm volatile("ldmatrix.sync.aligned.m8n8.x4.shared.b16 {%0,%1,%2,%3}, [%4];"
        : "=r"(r[0]), "=r"(r[1]), "=r"(r[2]), "=r"(r[3]) : "r"(addr));
}
__device__ __forceinline__ void mma16816(float (&c)[4], const uint32_t (&a)[4],
                                         const uint32_t* b) {
    asm volatile(
        "mma.sync.aligned.m16n8k16.row.col.f32.bf16.bf16.f32 "
        "{%0,%1,%2,%3}, {%4,%5,%6,%7}, {%8,%9}, {%0,%1,%2,%3};"
        : "+f"(c[0]), "+f"(c[1]), "+f"(c[2]), "+f"(c[3])
        : "r"(a[0]), "r"(a[1]), "r"(a[2]), "r"(a[3]), "r"(b[0]), "r"(b[1]));
}

// ---------------------------------------------------------------------------
// SMEM tiles: BM=128, BN=256, BK=64. Row stride 144B -> bank-group of chunk
// (r,c) = (r+c) mod 8 -> conflict-free ldmatrix, no swizzle needed.
// ---------------------------------------------------------------------------
#define ROWB 144u
#define TILE_A (128u * ROWB)          // 18432
#define TILE_Bt (256u * ROWB)         // 36864
#define OFF_AH 0u
#define OFF_AL TILE_A
#define OFF_BH (2u * TILE_A)
#define OFF_BL (2u * TILE_A + TILE_Bt)
#define BUF_STRIDE (2u * TILE_A + 2u * TILE_Bt)  // 110592
#define SMEM_G (2 * 110592)                      // 221184

#define NTHREADS 512

__device__ __forceinline__ void load_partA(uint32_t sbase, const __nv_bfloat16* __restrict__ g,
                                           int ld, int k0) {
    const int t = threadIdx.x;
    #pragma unroll
    for (int i = 0; i < 2; i++) {
        int u = t + i * NTHREADS;
        int row = u >> 3, c = u & 7;
        cp16(sbase + (uint32_t)row * ROWB + (uint32_t)c * 16,
             g + (size_t)row * ld + k0 + c * 8);
    }
}
__device__ __forceinline__ void load_partB(uint32_t sbase, const __nv_bfloat16* __restrict__ g,
                                           int ld, int k0) {
    const int t = threadIdx.x;
    #pragma unroll
    for (int i = 0; i < 4; i++) {
        int u = t + i * NTHREADS;
        int row = u >> 3, c = u & 7;
        cp16(sbase + (uint32_t)row * ROWB + (uint32_t)c * 16,
             g + (size_t)row * ld + k0 + c * 8);
    }
}
__device__ __forceinline__ void load_chunk(uint32_t buf,
    const __nv_bfloat16* Ah, const __nv_bfloat16* Al, int lda,
    const __nv_bfloat16* Bh, const __nv_bfloat16* Bl, int ldb, int k0) {
    load_partA(buf + OFF_AH, Ah, lda, k0);
    load_partA(buf + OFF_AL, Al, lda, k0);
    load_partB(buf + OFF_BH, Bh, ldb, k0);
    load_partB(buf + OFF_BL, Bl, ldb, k0);
}

// Compute one BK=64 chunk (warp tile 64x32), 3-term split, two-phase A regs.
__device__ __forceinline__ void compute_chunk(uint32_t buf, float (&acc)[4][4][4],
                                              int m0, int n0, int lane) {
    const uint32_t aBase = buf + OFF_AH
        + (uint32_t)(m0 + (lane & 15)) * ROWB + (uint32_t)(lane >> 4) * 16u;
    const uint32_t bRow = (uint32_t)((lane & 7) + ((lane >> 4) & 1) * 8);
    const uint32_t bBase = buf + OFF_BH
        + (uint32_t)(n0 + bRow) * ROWB + (uint32_t)((lane >> 3) & 1) * 16u;
    #pragma unroll
    for (int ks = 0; ks < 4; ks++) {
        uint32_t bh[4][2], bl[4][2];
        #pragma unroll
        for (int np = 0; np < 2; np++) {
            uint32_t r[4];
            ldsm_x4(r, bBase + (uint32_t)(np * 16) * ROWB + ks * 32u);
            bh[2 * np][0] = r[0]; bh[2 * np][1] = r[1];
            bh[2 * np + 1][0] = r[2]; bh[2 * np + 1][1] = r[3];
            ldsm_x4(r, bBase + (OFF_BL - OFF_BH) + (uint32_t)(np * 16) * ROWB + ks * 32u);
            bl[2 * np][0] = r[0]; bl[2 * np][1] = r[1];
            bl[2 * np + 1][0] = r[2]; bl[2 * np + 1][1] = r[3];
        }
        {
            uint32_t a[4][4];
            #pragma unroll
            for (int mt = 0; mt < 4; mt++)
                ldsm_x4(a[mt], aBase + (uint32_t)(mt * 16) * ROWB + ks * 32u);
            #pragma unroll
            for (int mt = 0; mt < 4; mt++)
                #pragma unroll
                for (int nt = 0; nt < 4; nt++) {
                    mma16816(acc[mt][nt], a[mt], bh[nt]);   // hi*hi
                    mma16816(acc[mt][nt], a[mt], bl[nt]);   // hi*lo
                }
            #pragma unroll
            for (int mt = 0; mt < 4; mt++)
                ldsm_x4(a[mt], aBase + (OFF_AL - OFF_AH) + (uint32_t)(mt * 16) * ROWB + ks * 32u);
            #pragma unroll
            for (int mt = 0; mt < 4; mt++)
                #pragma unroll
                for (int nt = 0; nt < 4; nt++)
                    mma16816(acc[mt][nt], a[mt], bh[nt]);   // lo*hi
        }
    }
}

// Mainloop: C[128,256] += A[128,kEnd] @ B[256,kEnd]^T (split-bf16, fp32 acc)
__device__ __forceinline__ void gemm_mainloop(
    const __nv_bfloat16* Ah, const __nv_bfloat16* Al, int lda,
    const __nv_bfloat16* Bh, const __nv_bfloat16* Bl, int ldb,
    int kEnd, float (&acc)[4][4][4]) {
    extern __shared__ char smem[];
    const uint32_t sb = smem_u32(smem);
    const int lane = threadIdx.x & 31;
    const int wid  = threadIdx.x >> 5;
    const int m0 = (wid >> 3) * 64;
    const int n0 = (wid & 7) * 32;

    load_chunk(sb, Ah, Al, lda, Bh, Bl, ldb, 0);
    CP_COMMIT();
    const int nc = kEnd >> 6;
    for (int c = 0; c < nc; c++) {
        const uint32_t buf = sb + (uint32_t)(c & 1) * BUF_STRIDE;
        CP_WAIT0();
        __syncthreads();
        if (c + 1 < nc) {
            load_chunk(sb + (uint32_t)((c + 1) & 1) * BUF_STRIDE,
                       Ah, Al, lda, Bh, Bl, ldb, (c + 1) << 6);
            CP_COMMIT();
        }
        compute_chunk(buf, acc, m0, n0, lane);
    }
}

// ---------------------------------------------------------------------------
// fp32 -> bf16 hi/lo split
// ---------------------------------------------------------------------------
__device__ __forceinline__ void split_bf16(float v, __nv_bfloat16& h, __nv_bfloat16& l) {
    h = __float2bfloat16(v);
    l = __float2bfloat16(v - __bfloat162float(h));
}
__device__ __forceinline__ void store_pair(__nv_bfloat16* oh, __nv_bfloat16* ol,
                                           size_t o, float f0, float f1) {
    __nv_bfloat16 h0, l0, h1, l1;
    split_bf16(f0, h0, l0);
    split_bf16(f1, h1, l1);
    *(uint32_t*)(oh + o) = ((uint32_t)__bfloat16_as_ushort(h1) << 16) | __bfloat16_as_ushort(h0);
    *(uint32_t*)(ol + o) = ((uint32_t)__bfloat16_as_ushort(l1) << 16) | __bfloat16_as_ushort(l0);
}

// Epilogue: raw fp32 store into [rows x D] scratch.
__device__ __forceinline__ void epi_f32_store(
    float (&acc)[4][4][4], float* __restrict__ o, int bm, int bn) {
    const int lane = threadIdx.x & 31, wid = threadIdx.x >> 5;
    const int m0 = bm + (wid >> 3) * 64, n0 = bn + (wid & 7) * 32;
    const int g = lane >> 2, tig = lane & 3;
    #pragma unroll
    for (int mt = 0; mt < 4; mt++)
        #pragma unroll
        for (int nt = 0; nt < 4; nt++)
            #pragma unroll
            for (int h = 0; h < 2; h++) {
                int row = m0 + mt * 16 + g + h * 8;
                int col = n0 + nt * 8 + tig * 2;
                *(float2*)(o + (size_t)row * D_ + col) =
                    make_float2(acc[mt][nt][2 * h], acc[mt][nt][2 * h + 1]);
            }
}

// ---------------------------------------------------------------------------
// pack kernels
// ---------------------------------------------------------------------------
__global__ void pack_xz(const float* __restrict__ zr, const float* __restrict__ zi) {
    int idx = blockIdx.x * 256 + threadIdx.x;       // < M_*D_
    int m = idx >> 10, k = idx & 1023;
    float vr = zr[idx], vi = zi[idx];
    size_t o = (size_t)m * K2_ + k;
    split_bf16(vr, g_Xh[o], g_Xl[o]);
    split_bf16(vi, g_Xh[o + D_], g_Xl[o + D_]);
    split_bf16(vr + vi, g_Zsh[idx], g_Zsl[idx]);
}
__global__ void pack_wT(const float* __restrict__ wqr, const float* __restrict__ wqi,
                        const float* __restrict__ wkr, const float* __restrict__ wki) {
    const int which = blockIdx.z;
    const float* wr = which ? wkr : wqr;
    const float* wi = which ? wki : wqi;
    __nv_bfloat16* oh = which ? g_WkTh : g_WqTh;
    __nv_bfloat16* ol = which ? g_WkTl : g_WqTl;
    const int i0 = blockIdx.x * 32, l0 = blockIdx.y * 32;
    const bool qi = i0 >= 1024, ql = l0 >= 1024;
    const float* src = (qi == ql) ? wr : wi;
    const float sign = (qi && !ql) ? -1.f : 1.f;
    const int r0 = l0 - (ql ? 1024 : 0), c0 = i0 - (qi ? 1024 : 0);
    __shared__ float t[32][33];
    const int tx = threadIdx.x, ty = threadIdx.y;
    #pragma unroll
    for (int j = 0; j < 32; j += 8)
        t[ty + j][tx] = src[(size_t)(r0 + ty + j) * 1024 + c0 + tx];
    __syncthreads();
    #pragma unroll
    for (int j = 0; j < 32; j += 8) {
        float v = sign * t[tx][ty + j];
        __nv_bfloat16 h, l;
        split_bf16(v, h, l);
        size_t o = (size_t)(i0 + ty + j) * K2_ + l0 + tx;
        oh[o] = h; ol[o] = l;
    }
}
__global__ void pack_ev(const float* __restrict__ wvr, const float* __restrict__ wvi) {
    int idx = blockIdx.x * 256 + threadIdx.x;       // < D_*D_
    float vr = wvr[idx], vi = wvi[idx];
    split_bf16(vr,      g_Evrh[idx], g_Evrl[idx]);
    split_bf16(vi,      g_Evih[idx], g_Evil[idx]);
    split_bf16(vr + vi, g_Evsh[idx], g_Evsl[idx]);
}

// ---------------------------------------------------------------------------
// GEMM G (k-split): partial[kh] = Wq~^T @ Wk~[:, 0:1024] over K half kh
// grid(4, 16, 2) = 128 CTAs. Partials in g_M1u (kh=0) / g_M2u (kh=1).
// ---------------------------------------------------------------------------
__global__ void __launch_bounds__(NTHREADS) k_gemm_G() {
    float acc[4][4][4] = {};
    const int bm = blockIdx.y * 128, bn = blockIdx.x * 256;
    const int koff = blockIdx.z * 1024;
    gemm_mainloop(g_WqTh + (size_t)bm * K2_ + koff, g_WqTl + (size_t)bm * K2_ + koff, K2_,
                  g_WkTh + (size_t)bn * K2_ + koff, g_WkTl + (size_t)bn * K2_ + koff, K2_,
                  1024, acc);
    epi_f32_store(acc, blockIdx.z ? g_M2u : g_M1u, bm, bn);
}

// Reduce G partials -> Gh/Gl (both Gr and Gi rows) + Gs = Gr+Gi.  grid(4096)
__global__ void reduce_G() {
    int idx = blockIdx.x * 256 + threadIdx.x;       // < D_*D_ (Gr element)
    const size_t DD = (size_t)D_ * D_;
    float gr = g_M1u[idx] + g_M2u[idx];
    float gi = g_M1u[idx + DD] + g_M2u[idx + DD];
    split_bf16(gr, g_Gh[idx], g_Gl[idx]);
    split_bf16(gi, g_Gh[idx + DD], g_Gl[idx + DD]);
    split_bf16(gr + gi, g_Gsh[idx], g_Gsl[idx]);
}

// ---------------------------------------------------------------------------
// Karatsuba M1/M2 for U and V, merged.  grid(16, 64)
// quad 0: U-M1 = Zr x Gr | 1: U-M2 = Zi x Gi | 2: V-M1 = Zr x Er | 3: V-M2 = Zi x Ei
// ---------------------------------------------------------------------------
__global__ void __launch_bounds__(NTHREADS) k_gemm_M12() {
    float acc[4][4][4] = {};
    const int quad = blockIdx.x >> 2;
    const int bn = (blockIdx.x & 3) * 256;
    const int bm = blockIdx.y * 128;
    const int aoff = (quad & 1) ? D_ : 0;
    const __nv_bfloat16 *Bh, *Bl;
    float* out;
    switch (quad) {
        case 0: Bh = g_Gh;            Bl = g_Gl;            out = g_M1u; break;
        case 1: Bh = g_Gh + (size_t)D_ * D_; Bl = g_Gl + (size_t)D_ * D_; out = g_M2u; break;
        case 2: Bh = g_Evrh;          Bl = g_Evrl;          out = g_M1v; break;
        default:Bh = g_Evih;          Bl = g_Evil;          out = g_M2v; break;
    }
    gemm_mainloop(g_Xh + (size_t)bm * K2_ + aoff, g_Xl + (size_t)bm * K2_ + aoff, K2_,
                  Bh + (size_t)bn * D_, Bl + (size_t)bn * D_, D_, D_, acc);
    epi_f32_store(acc, out, bm, bn);
}

// ---------------------------------------------------------------------------
// Karatsuba M3 + closer.  grid(8, 64)
// half 0: U-M3 = Zs x Gs -> U = [M1-M2 | M3-M1-M2] (row-major)
// half 1: V-M3 = Zs x Es -> Vt (TRANSPOSED scatter; vtrans eliminated)
// ---------------------------------------------------------------------------
__global__ void __launch_bounds__(NTHREADS) k_gemm_M3() {
    float acc[4][4][4] = {};
    const int half = blockIdx.x >> 2;
    const int bn = (blockIdx.x & 3) * 256;
    const int bm = blockIdx.y * 128;
    const __nv_bfloat16* Bh = half ? g_Evsh : g_Gsh;
    const __nv_bfloat16* Bl = half ? g_Evsl : g_Gsl;
    gemm_mainloop(g_Zsh + (size_t)bm * D_, g_Zsl + (size_t)bm * D_, D_,
                  Bh + (size_t)bn * D_, Bl + (size_t)bn * D_, D_, D_, acc);
    const float* M1 = half ? g_M1v : g_M1u;
    const float* M2 = half ? g_M2v : g_M2u;
    const int lane = threadIdx.x & 31, wid = threadIdx.x >> 5;
    const int m0 = bm + (wid >> 3) * 64, n0 = bn + (wid & 7) * 32;
    const int g = lane >> 2, tig = lane & 3;
    if (half == 0) {
        #pragma unroll
        for (int mt = 0; mt < 4; mt++)
            #pragma unroll
            for (int nt = 0; nt < 4; nt++)
                #pragma unroll
                for (int h = 0; h < 2; h++) {
                    int row = m0 + mt * 16 + g + h * 8;
                    int col = n0 + nt * 8 + tig * 2;
                    float2 m1 = *(const float2*)(M1 + (size_t)row * D_ + col);
                    float2 m2 = *(const float2*)(M2 + (size_t)row * D_ + col);
                    float a0 = acc[mt][nt][2 * h], a1 = acc[mt][nt][2 * h + 1];
                    store_pair(g_Uh, g_Ul, (size_t)row * K2_ + col, m1.x - m2.x, m1.y - m2.y);
                    store_pair(g_Uh, g_Ul, (size_t)row * K2_ + D_ + col,
                               a0 - m1.x - m2.x, a1 - m1.y - m2.y);
                }
    } else {
        // Transposed scatter into Vt[b][d'][t], t = row % S.  Quarter-warp
        // lanes (g=0..7) give 8 consecutive t per (col,h) -> 16B runs.
        #pragma unroll
        for (int mt = 0; mt < 4; mt++)
            #pragma unroll
            for (int nt = 0; nt < 4; nt++)
                #pragma unroll
                for (int h = 0; h < 2; h++) {
                    int row = m0 + mt * 16 + g + h * 8;
                    int col = n0 + nt * 8 + tig * 2;
                    int bb = row >> 11, t = row & 2047;
                    float2 m1 = *(const float2*)(M1 + (size_t)row * D_ + col);
                    float2 m2 = *(const float2*)(M2 + (size_t)row * D_ + col);
                    float a0 = acc[mt][nt][2 * h], a1 = acc[mt][nt][2 * h + 1];
                    float re0 = m1.x - m2.x,      re1 = m1.y - m2.y;
                    float im0 = a0 - m1.x - m2.x, im1 = a1 - m1.y - m2.y;
                    size_t base = (size_t)bb * K2_ * S_ + t;
                    __nv_bfloat16 hh, ll;
                    split_bf16(re0, hh, ll);
                    g_Vth[base + (size_t)col * S_] = hh;       g_Vtl[base + (size_t)col * S_] = ll;
                    split_bf16(re1, hh, ll);
                    g_Vth[base + (size_t)(col + 1) * S_] = hh; g_Vtl[base + (size_t)(col + 1) * S_] = ll;
                    split_bf16(im0, hh, ll);
                    g_Vth[base + (size_t)(col + D_) * S_] = hh;     g_Vtl[base + (size_t)(col + D_) * S_] = ll;
                    split_bf16(im1, hh, ll);
                    g_Vth[base + (size_t)(col + D_ + 1) * S_] = hh; g_Vtl[base + (size_t)(col + D_ + 1) * S_] = ll;
                }
    }
}

// ---------------------------------------------------------------------------
// GEMM scores: scores = Z~ @ U^T, causal tile skip   grid(8,16,4)
// ---------------------------------------------------------------------------
__global__ void __launch_bounds__(NTHREADS) k_gemm_scores() {
    if ((int)blockIdx.x * 2 > (int)blockIdx.y) return;
    float acc[4][4][4] = {};
    const int b = blockIdx.z, bm = blockIdx.y * 128, bn = blockIdx.x * 256;
    gemm_mainloop(g_Xh + ((size_t)(b * S_ + bm)) * K2_,
                  g_Xl + ((size_t)(b * S_ + bm)) * K2_, K2_,
                  g_Uh + ((size_t)(b * S_ + bn)) * K2_,
                  g_Ul + ((size_t)(b * S_ + bn)) * K2_, K2_, K2_, acc);
    const int lane = threadIdx.x & 31, wid = threadIdx.x >> 5;
    const int m0 = bm + (wid >> 3) * 64, n0 = bn + (wid & 7) * 32;
    const int g = lane >> 2, tig = lane & 3;
    float* C = g_P + (size_t)b * S_ * S_;
    #pragma unroll
    for (int mt = 0; mt < 4; mt++)
        #pragma unroll
        for (int nt = 0; nt < 4; nt++)
            #pragma unroll
            for (int h = 0; h < 2; h++) {
                int row = m0 + mt * 16 + g + h * 8;
                int col = n0 + nt * 8 + tig * 2;
                *(float2*)(C + (size_t)row * S_ + col) =
                    make_float2(acc[mt][nt][2 * h], acc[mt][nt][2 * h + 1]);
            }
}

// ---------------------------------------------------------------------------
// Causal softmax: g_P -> g_Ph/g_Pl (bf16 hi/lo, zero-padded to 128 boundary)
// ---------------------------------------------------------------------------
__global__ void __launch_bounds__(256) softmax_k() {
    const int b = blockIdx.y, s = blockIdx.x;
    const float* row = g_P + ((size_t)(b * S_ + s)) * S_;
    __nv_bfloat16* oh = g_Ph + ((size_t)(b * S_ + s)) * S_;
    __nv_bfloat16* ol = g_Pl + ((size_t)(b * S_ + s)) * S_;
    const int n = s + 1;
    const int lim = ((s >> 7) + 1) << 7;
    const float scale = 0.03125f;
    __shared__ float red[256];
    const int tid = threadIdx.x;

    float ev[8];
    float m = -3.0e38f;
    #pragma unroll
    for (int it = 0; it < 8; it++) {
        int i = tid + it * 256;
        float v = (i < n) ? row[i] : -3.0e38f;
        ev[it] = v;
        m = fmaxf(m, v);
    }
    red[tid] = m; __syncthreads();
    for (int off = 128; off > 0; off >>= 1) {
        if (tid < off) red[tid] = fmaxf(red[tid], red[tid + off]);
        __syncthreads();
    }
    const float mv = red[0] * scale;
    __syncthreads();

    float sum = 0.f;
    #pragma unroll
    for (int it = 0; it < 8; it++) {
        int i = tid + it * 256;
        float e = (i < n) ? __expf(ev[it] * scale - mv) : 0.f;
        ev[it] = e;
        sum += e;
    }
    red[tid] = sum; __syncthreads();
    for (int off = 128; off > 0; off >>= 1) {
        if (tid < off) red[tid] += red[tid + off];
        __syncthreads();
    }
    const float inv = 1.0f / red[0];

    #pragma unroll
    for (int it = 0; it < 8; it++) {
        int i = tid + it * 256;
        if (i < lim) {
            float p = (i < n) ? ev[it] * inv : 0.f;
            __nv_bfloat16 h, l;
            split_bf16(p, h, l);
            oh[i] = h; ol[i] = l;
        }
    }
}

// ---------------------------------------------------------------------------
// GEMM PV: Out = P @ Vt^T (causal K-limit), heavy tiles first  grid(8,16,4)
// ---------------------------------------------------------------------------
__global__ void __launch_bounds__(NTHREADS) k_gemm_pv(float* __restrict__ out) {
    float acc[4][4][4] = {};
    const int b = blockIdx.z;
    const int bm = (15 - (int)blockIdx.y) * 128;   // heavy-first
    const int bn = blockIdx.x * 256;
    gemm_mainloop(g_Ph + ((size_t)(b * S_ + bm)) * S_,
                  g_Pl + ((size_t)(b * S_ + bm)) * S_, S_,
                  g_Vth + ((size_t)b * K2_ + bn) * S_,
                  g_Vtl + ((size_t)b * K2_ + bn) * S_, S_,
                  bm + 128, acc);
    const int lane = threadIdx.x & 31, wid = threadIdx.x >> 5;
    const int m0 = bm + (wid >> 3) * 64, n0 = bn + (wid & 7) * 32;
    const int g = lane >> 2, tig = lane & 3;
    #pragma unroll
    for (int mt = 0; mt < 4; mt++)
        #pragma unroll
        for (int nt = 0; nt < 4; nt++)
            #pragma unroll
            for (int h = 0; h < 2; h++) {
                int s = m0 + mt * 16 + g + h * 8;
                int col = n0 + nt * 8 + tig * 2;
                int plane = col >> 10, d = col & 1023;
                *(float2*)(out + (((size_t)plane * B_ + b) * S_ + s) * (size_t)D_ + d) =
                    make_float2(acc[mt][nt][2 * h], acc[mt][nt][2 * h + 1]);
            }
}

// ---------------------------------------------------------------------------
// Launch
// ---------------------------------------------------------------------------
extern "C" void kernel_launch(void* const* d_in, const int* in_sizes, int n_in,
                              void* d_out, int out_size) {
    const float* z_real = (const float*)d_in[0];
    const float* z_imag = (const float*)d_in[1];
    const float* wq_r   = (const float*)d_in[2];
    const float* wq_i   = (const float*)d_in[3];
    const float* wk_r   = (const float*)d_in[4];
    const float* wk_i   = (const float*)d_in[5];
    const float* wv_r   = (const float*)d_in[6];
    const float* wv_i   = (const float*)d_in[7];
    float* out = (float*)d_out;

    static int attr_done = 0;
    if (!attr_done) {
        cudaFuncSetAttribute(k_gemm_G,      cudaFuncAttributeMaxDynamicSharedMemorySize, SMEM_G);
        cudaFuncSetAttribute(k_gemm_M12,    cudaFuncAttributeMaxDynamicSharedMemorySize, SMEM_G);
        cudaFuncSetAttribute(k_gemm_M3,     cudaFuncAttributeMaxDynamicSharedMemorySize, SMEM_G);
        cudaFuncSetAttribute(k_gemm_scores, cudaFuncAttributeMaxDynamicSharedMemorySize, SMEM_G);
        cudaFuncSetAttribute(k_gemm_pv,     cudaFuncAttributeMaxDynamicSharedMemorySize, SMEM_G);
        attr_done = 1;
    }

    pack_xz<<<(M_ * D_) / 256, 256>>>(z_real, z_imag);
    pack_wT<<<dim3(64, 64, 2), dim3(32, 8)>>>(wq_r, wq_i, wk_r, wk_i);
    pack_ev<<<(D_ * D_) / 256, 256>>>(wv_r, wv_i);
    k_gemm_G<<<dim3(D_ / 256, K2_ / 128, 2), NTHREADS, SMEM_G>>>();
    reduce_G<<<(D_ * D_) / 256, 256>>>();
    k_gemm_M12<<<dim3(16, M_ / 128), NTHREADS, SMEM_G>>>();
    k_gemm_M3<<<dim3(8, M_ / 128), NTHREADS, SMEM_G>>>();
    k_gemm_scores<<<dim3(S_ / 256, S_ / 128, B_), NTHREADS, SMEM_G>>>();
    softmax_k<<<dim3(S_, B_), 256>>>();
    k_gemm_pv<<<dim3(K2_ / 256, S_ / 128, B_), NTHREADS, SMEM_G>>>(out);
}

// round 17
// speedup vs baseline: 1.0604x; 1.0014x over previous
#include <cuda_runtime.h>
#include <cuda_bf16.h>
#include <cstdint>
#include <cstddef>

// Problem constants
#define B_  4
#define S_  2048
#define D_  1024
#define M_  (B_ * S_)     // 8192
#define K2_ (2 * D_)      // 2048

// ---------------------------------------------------------------------------
// Scratch (static __device__ — no allocations allowed)
// ---------------------------------------------------------------------------
__device__ __nv_bfloat16 g_Xh [(size_t)M_  * K2_];   // z-cat hi
__device__ __nv_bfloat16 g_Xl [(size_t)M_  * K2_];
__device__ __nv_bfloat16 g_Zsh[(size_t)M_  * D_];    // zr+zi hi/lo
__device__ __nv_bfloat16 g_Zsl[(size_t)M_  * D_];
__device__ __nv_bfloat16 g_WqTh[(size_t)K2_ * K2_];
__device__ __nv_bfloat16 g_WqTl[(size_t)K2_ * K2_];
__device__ __nv_bfloat16 g_WkTh[(size_t)K2_ * K2_];
__device__ __nv_bfloat16 g_WkTl[(size_t)K2_ * K2_];
__device__ __nv_bfloat16 g_Gh [(size_t)K2_ * D_];    // G~ left half: Gr rows 0:1024, Gi rows 1024:2048 (ld=D)
__device__ __nv_bfloat16 g_Gl [(size_t)K2_ * D_];
__device__ __nv_bfloat16 g_Gsh[(size_t)D_ * D_];     // Gr+Gi
__device__ __nv_bfloat16 g_Gsl[(size_t)D_ * D_];
__device__ __nv_bfloat16 g_Evrh[(size_t)D_ * D_];    // wv_r split
__device__ __nv_bfloat16 g_Evrl[(size_t)D_ * D_];
__device__ __nv_bfloat16 g_Evih[(size_t)D_ * D_];    // wv_i split
__device__ __nv_bfloat16 g_Evil[(size_t)D_ * D_];
__device__ __nv_bfloat16 g_Evsh[(size_t)D_ * D_];    // wv_r+wv_i split
__device__ __nv_bfloat16 g_Evsl[(size_t)D_ * D_];
__device__ float g_M1u[(size_t)M_ * D_];             // Karatsuba fp32 scratch (also G k-split partials)
__device__ float g_M2u[(size_t)M_ * D_];
__device__ float g_M1v[(size_t)M_ * D_];
__device__ float g_M2v[(size_t)M_ * D_];
__device__ __nv_bfloat16 g_Uh [(size_t)M_  * K2_];   // U concat [Ur|Ui]
__device__ __nv_bfloat16 g_Ul [(size_t)M_  * K2_];
__device__ __nv_bfloat16 g_Vth[(size_t)B_ * K2_ * S_]; // V transposed [b][d'][t]
__device__ __nv_bfloat16 g_Vtl[(size_t)B_ * K2_ * S_];
__device__ float         g_P  [(size_t)B_ * S_ * S_];
__device__ __nv_bfloat16 g_Ph [(size_t)B_ * S_ * S_];
__device__ __nv_bfloat16 g_Pl [(size_t)B_ * S_ * S_];

// ---------------------------------------------------------------------------
// PTX helpers (sm_80-era only — NO tcgen05: harness targets plain sm_103)
// ---------------------------------------------------------------------------
__device__ __forceinline__ uint32_t smem_u32(const void* p) {
    uint32_t a;
    asm("{ .reg .u64 t; cvta.to.shared.u64 t, %1; cvt.u32.u64 %0, t; }" : "=r"(a) : "l"(p));
    return a;
}
__device__ __forceinline__ void cp16(uint32_t saddr, const void* gaddr) {
    asm volatile("cp.async.cg.shared.global [%0], [%1], 16;" :: "r"(saddr), "l"(gaddr));
}
#define CP_COMMIT() asm volatile("cp.async.commit_group;" ::: "memory")
#define CP_WAIT0()  asm volatile("cp.async.wait_group 0;" ::: "memory")

__device__ __forceinline__ void ldsm_x4(uint32_t (&r)[4], uint32_t addr) {
    asm volatile("ldmatrix.sync.aligned.m8n8.x4.shared.b16 {%0,%1,%2,%3}, [%4];"
        : "=r"(r[0]), "=r"(r[1]), "=r"(r[2]), "=r"(r[3]) : "r"(addr));
}
__device__ __forceinline__ void mma16816(float (&c)[4], const uint32_t (&a)[4],
                                         const uint32_t* b) {
    asm volatile(
        "mma.sync.aligned.m16n8k16.row.col.f32.bf16.bf16.f32 "
        "{%0,%1,%2,%3}, {%4,%5,%6,%7}, {%8,%9}, {%0,%1,%2,%3};"
        : "+f"(c[0]), "+f"(c[1]), "+f"(c[2]), "+f"(c[3])
        : "r"(a[0]), "r"(a[1]), "r"(a[2]), "r"(a[3]), "r"(b[0]), "r"(b[1]));
}

// ---------------------------------------------------------------------------
// SMEM tiles: BM=128, BN=256, BK=64. Row stride 144B -> bank-group of chunk
// (r,c) = (r+c) mod 8 -> conflict-free ldmatrix, no swizzle needed.
// ---------------------------------------------------------------------------
#define ROWB 144u
#define TILE_A (128u * ROWB)          // 18432
#define TILE_Bt (256u * ROWB)         // 36864
#define OFF_AH 0u
#define OFF_AL TILE_A
#define OFF_BH (2u * TILE_A)
#define OFF_BL (2u * TILE_A + TILE_Bt)
#define BUF_STRIDE (2u * TILE_A + 2u * TILE_Bt)  // 110592
#define SMEM_G (2 * 110592)                      // 221184

#define NTHREADS 512

__device__ __forceinline__ void load_partA(uint32_t sbase, const __nv_bfloat16* __restrict__ g,
                                           int ld, int k0) {
    const int t = threadIdx.x;
    #pragma unroll
    for (int i = 0; i < 2; i++) {
        int u = t + i * NTHREADS;
        int row = u >> 3, c = u & 7;
        cp16(sbase + (uint32_t)row * ROWB + (uint32_t)c * 16,
             g + (size_t)row * ld + k0 + c * 8);
    }
}
__device__ __forceinline__ void load_partB(uint32_t sbase, const __nv_bfloat16* __restrict__ g,
                                           int ld, int k0) {
    const int t = threadIdx.x;
    #pragma unroll
    for (int i = 0; i < 4; i++) {
        int u = t + i * NTHREADS;
        int row = u >> 3, c = u & 7;
        cp16(sbase + (uint32_t)row * ROWB + (uint32_t)c * 16,
             g + (size_t)row * ld + k0 + c * 8);
    }
}
__device__ __forceinline__ void load_chunk(uint32_t buf,
    const __nv_bfloat16* Ah, const __nv_bfloat16* Al, int lda,
    const __nv_bfloat16* Bh, const __nv_bfloat16* Bl, int ldb, int k0) {
    load_partA(buf + OFF_AH, Ah, lda, k0);
    load_partA(buf + OFF_AL, Al, lda, k0);
    load_partB(buf + OFF_BH, Bh, ldb, k0);
    load_partB(buf + OFF_BL, Bl, ldb, k0);
}

// Compute one BK=64 chunk (warp tile 64x32), 3-term split, two-phase A regs.
__device__ __forceinline__ void compute_chunk(uint32_t buf, float (&acc)[4][4][4],
                                              int m0, int n0, int lane) {
    const uint32_t aBase = buf + OFF_AH
        + (uint32_t)(m0 + (lane & 15)) * ROWB + (uint32_t)(lane >> 4) * 16u;
    const uint32_t bRow = (uint32_t)((lane & 7) + ((lane >> 4) & 1) * 8);
    const uint32_t bBase = buf + OFF_BH
        + (uint32_t)(n0 + bRow) * ROWB + (uint32_t)((lane >> 3) & 1) * 16u;
    #pragma unroll
    for (int ks = 0; ks < 4; ks++) {
        uint32_t bh[4][2], bl[4][2];
        #pragma unroll
        for (int np = 0; np < 2; np++) {
            uint32_t r[4];
            ldsm_x4(r, bBase + (uint32_t)(np * 16) * ROWB + ks * 32u);
            bh[2 * np][0] = r[0]; bh[2 * np][1] = r[1];
            bh[2 * np + 1][0] = r[2]; bh[2 * np + 1][1] = r[3];
            ldsm_x4(r, bBase + (OFF_BL - OFF_BH) + (uint32_t)(np * 16) * ROWB + ks * 32u);
            bl[2 * np][0] = r[0]; bl[2 * np][1] = r[1];
            bl[2 * np + 1][0] = r[2]; bl[2 * np + 1][1] = r[3];
        }
        {
            uint32_t a[4][4];
            #pragma unroll
            for (int mt = 0; mt < 4; mt++)
                ldsm_x4(a[mt], aBase + (uint32_t)(mt * 16) * ROWB + ks * 32u);
            #pragma unroll
            for (int mt = 0; mt < 4; mt++)
                #pragma unroll
                for (int nt = 0; nt < 4; nt++) {
                    mma16816(acc[mt][nt], a[mt], bh[nt]);   // hi*hi
                    mma16816(acc[mt][nt], a[mt], bl[nt]);   // hi*lo
                }
            #pragma unroll
            for (int mt = 0; mt < 4; mt++)
                ldsm_x4(a[mt], aBase + (OFF_AL - OFF_AH) + (uint32_t)(mt * 16) * ROWB + ks * 32u);
            #pragma unroll
            for (int mt = 0; mt < 4; mt++)
                #pragma unroll
                for (int nt = 0; nt < 4; nt++)
                    mma16816(acc[mt][nt], a[mt], bh[nt]);   // lo*hi
        }
    }
}

// Mainloop: C[128,256] += A[128,kEnd] @ B[256,kEnd]^T (split-bf16, fp32 acc)
__device__ __forceinline__ void gemm_mainloop(
    const __nv_bfloat16* Ah, const __nv_bfloat16* Al, int lda,
    const __nv_bfloat16* Bh, const __nv_bfloat16* Bl, int ldb,
    int kEnd, float (&acc)[4][4][4]) {
    extern __shared__ char smem[];
    const uint32_t sb = smem_u32(smem);
    const int lane = threadIdx.x & 31;
    const int wid  = threadIdx.x >> 5;
    const int m0 = (wid >> 3) * 64;
    const int n0 = (wid & 7) * 32;

    load_chunk(sb, Ah, Al, lda, Bh, Bl, ldb, 0);
    CP_COMMIT();
    const int nc = kEnd >> 6;
    for (int c = 0; c < nc; c++) {
        const uint32_t buf = sb + (uint32_t)(c & 1) * BUF_STRIDE;
        CP_WAIT0();
        __syncthreads();
        if (c + 1 < nc) {
            load_chunk(sb + (uint32_t)((c + 1) & 1) * BUF_STRIDE,
                       Ah, Al, lda, Bh, Bl, ldb, (c + 1) << 6);
            CP_COMMIT();
        }
        compute_chunk(buf, acc, m0, n0, lane);
    }
}

// ---------------------------------------------------------------------------
// fp32 -> bf16 hi/lo split
// ---------------------------------------------------------------------------
__device__ __forceinline__ void split_bf16(float v, __nv_bfloat16& h, __nv_bfloat16& l) {
    h = __float2bfloat16(v);
    l = __float2bfloat16(v - __bfloat162float(h));
}
__device__ __forceinline__ void store_pair(__nv_bfloat16* oh, __nv_bfloat16* ol,
                                           size_t o, float f0, float f1) {
    __nv_bfloat16 h0, l0, h1, l1;
    split_bf16(f0, h0, l0);
    split_bf16(f1, h1, l1);
    *(uint32_t*)(oh + o) = ((uint32_t)__bfloat16_as_ushort(h1) << 16) | __bfloat16_as_ushort(h0);
    *(uint32_t*)(ol + o) = ((uint32_t)__bfloat16_as_ushort(l1) << 16) | __bfloat16_as_ushort(l0);
}

// Epilogue: raw fp32 store into [rows x D] scratch.
__device__ __forceinline__ void epi_f32_store(
    float (&acc)[4][4][4], float* __restrict__ o, int bm, int bn) {
    const int lane = threadIdx.x & 31, wid = threadIdx.x >> 5;
    const int m0 = bm + (wid >> 3) * 64, n0 = bn + (wid & 7) * 32;
    const int g = lane >> 2, tig = lane & 3;
    #pragma unroll
    for (int mt = 0; mt < 4; mt++)
        #pragma unroll
        for (int nt = 0; nt < 4; nt++)
            #pragma unroll
            for (int h = 0; h < 2; h++) {
                int row = m0 + mt * 16 + g + h * 8;
                int col = n0 + nt * 8 + tig * 2;
                *(float2*)(o + (size_t)row * D_ + col) =
                    make_float2(acc[mt][nt][2 * h], acc[mt][nt][2 * h + 1]);
            }
}

// ---------------------------------------------------------------------------
// pack kernels
// ---------------------------------------------------------------------------
// Merged: blocks [0, 32768) do z packing; [32768, 36864) do wv packing.
__global__ void pack_misc(const float* __restrict__ zr, const float* __restrict__ zi,
                          const float* __restrict__ wvr, const float* __restrict__ wvi) {
    if (blockIdx.x < 32768) {
        int idx = blockIdx.x * 256 + threadIdx.x;       // < M_*D_
        int m = idx >> 10, k = idx & 1023;
        float vr = zr[idx], vi = zi[idx];
        size_t o = (size_t)m * K2_ + k;
        split_bf16(vr, g_Xh[o], g_Xl[o]);
        split_bf16(vi, g_Xh[o + D_], g_Xl[o + D_]);
        split_bf16(vr + vi, g_Zsh[idx], g_Zsl[idx]);
    } else {
        int idx = (blockIdx.x - 32768) * 256 + threadIdx.x;  // < D_*D_
        float vr = wvr[idx], vi = wvi[idx];
        split_bf16(vr,      g_Evrh[idx], g_Evrl[idx]);
        split_bf16(vi,      g_Evih[idx], g_Evil[idx]);
        split_bf16(vr + vi, g_Evsh[idx], g_Evsl[idx]);
    }
}
__global__ void pack_wT(const float* __restrict__ wqr, const float* __restrict__ wqi,
                        const float* __restrict__ wkr, const float* __restrict__ wki) {
    const int which = blockIdx.z;
    const float* wr = which ? wkr : wqr;
    const float* wi = which ? wki : wqi;
    __nv_bfloat16* oh = which ? g_WkTh : g_WqTh;
    __nv_bfloat16* ol = which ? g_WkTl : g_WqTl;
    const int i0 = blockIdx.x * 32, l0 = blockIdx.y * 32;
    const bool qi = i0 >= 1024, ql = l0 >= 1024;
    const float* src = (qi == ql) ? wr : wi;
    const float sign = (qi && !ql) ? -1.f : 1.f;
    const int r0 = l0 - (ql ? 1024 : 0), c0 = i0 - (qi ? 1024 : 0);
    __shared__ float t[32][33];
    const int tx = threadIdx.x, ty = threadIdx.y;
    #pragma unroll
    for (int j = 0; j < 32; j += 8)
        t[ty + j][tx] = src[(size_t)(r0 + ty + j) * 1024 + c0 + tx];
    __syncthreads();
    #pragma unroll
    for (int j = 0; j < 32; j += 8) {
        float v = sign * t[tx][ty + j];
        __nv_bfloat16 h, l;
        split_bf16(v, h, l);
        size_t o = (size_t)(i0 + ty + j) * K2_ + l0 + tx;
        oh[o] = h; ol[o] = l;
    }
}

// ---------------------------------------------------------------------------
// GEMM G (k-split): partial[kh] = Wq~^T @ Wk~[:, 0:1024] over K half kh
// grid(4, 16, 2) = 128 CTAs. Partials in g_M1u (kh=0) / g_M2u (kh=1).
// ---------------------------------------------------------------------------
__global__ void __launch_bounds__(NTHREADS) k_gemm_G() {
    float acc[4][4][4] = {};
    const int bm = blockIdx.y * 128, bn = blockIdx.x * 256;
    const int koff = blockIdx.z * 1024;
    gemm_mainloop(g_WqTh + (size_t)bm * K2_ + koff, g_WqTl + (size_t)bm * K2_ + koff, K2_,
                  g_WkTh + (size_t)bn * K2_ + koff, g_WkTl + (size_t)bn * K2_ + koff, K2_,
                  1024, acc);
    epi_f32_store(acc, blockIdx.z ? g_M2u : g_M1u, bm, bn);
}

// Reduce G partials -> Gh/Gl (both Gr and Gi rows) + Gs = Gr+Gi.  grid(4096)
__global__ void reduce_G() {
    int idx = blockIdx.x * 256 + threadIdx.x;       // < D_*D_ (Gr element)
    const size_t DD = (size_t)D_ * D_;
    float gr = g_M1u[idx] + g_M2u[idx];
    float gi = g_M1u[idx + DD] + g_M2u[idx + DD];
    split_bf16(gr, g_Gh[idx], g_Gl[idx]);
    split_bf16(gi, g_Gh[idx + DD], g_Gl[idx + DD]);
    split_bf16(gr + gi, g_Gsh[idx], g_Gsl[idx]);
}

// ---------------------------------------------------------------------------
// Karatsuba M1/M2 for U and V, merged.  grid(16, 64)
// quad 0: U-M1 = Zr x Gr | 1: U-M2 = Zi x Gi | 2: V-M1 = Zr x Er | 3: V-M2 = Zi x Ei
// ---------------------------------------------------------------------------
__global__ void __launch_bounds__(NTHREADS) k_gemm_M12() {
    float acc[4][4][4] = {};
    const int quad = blockIdx.x >> 2;
    const int bn = (blockIdx.x & 3) * 256;
    const int bm = blockIdx.y * 128;
    const int aoff = (quad & 1) ? D_ : 0;
    const __nv_bfloat16 *Bh, *Bl;
    float* out;
    switch (quad) {
        case 0: Bh = g_Gh;            Bl = g_Gl;            out = g_M1u; break;
        case 1: Bh = g_Gh + (size_t)D_ * D_; Bl = g_Gl + (size_t)D_ * D_; out = g_M2u; break;
        case 2: Bh = g_Evrh;          Bl = g_Evrl;          out = g_M1v; break;
        default:Bh = g_Evih;          Bl = g_Evil;          out = g_M2v; break;
    }
    gemm_mainloop(g_Xh + (size_t)bm * K2_ + aoff, g_Xl + (size_t)bm * K2_ + aoff, K2_,
                  Bh + (size_t)bn * D_, Bl + (size_t)bn * D_, D_, D_, acc);
    epi_f32_store(acc, out, bm, bn);
}

// ---------------------------------------------------------------------------
// Karatsuba M3 + closer, U half.  grid(4, 64)
// U-M3 = Zs x Gs -> U = [M1-M2 | M3-M1-M2] (row-major)
// ---------------------------------------------------------------------------
__global__ void __launch_bounds__(NTHREADS) k_gemm_M3U() {
    float acc[4][4][4] = {};
    const int bn = blockIdx.x * 256;
    const int bm = blockIdx.y * 128;
    gemm_mainloop(g_Zsh + (size_t)bm * D_, g_Zsl + (size_t)bm * D_, D_,
                  g_Gsh + (size_t)bn * D_, g_Gsl + (size_t)bn * D_, D_, D_, acc);
    const int lane = threadIdx.x & 31, wid = threadIdx.x >> 5;
    const int m0 = bm + (wid >> 3) * 64, n0 = bn + (wid & 7) * 32;
    const int g = lane >> 2, tig = lane & 3;
    #pragma unroll
    for (int mt = 0; mt < 4; mt++)
        #pragma unroll
        for (int nt = 0; nt < 4; nt++)
            #pragma unroll
            for (int h = 0; h < 2; h++) {
                int row = m0 + mt * 16 + g + h * 8;
                int col = n0 + nt * 8 + tig * 2;
                float2 m1 = *(const float2*)(g_M1u + (size_t)row * D_ + col);
                float2 m2 = *(const float2*)(g_M2u + (size_t)row * D_ + col);
                float a0 = acc[mt][nt][2 * h], a1 = acc[mt][nt][2 * h + 1];
                store_pair(g_Uh, g_Ul, (size_t)row * K2_ + col, m1.x - m2.x, m1.y - m2.y);
                store_pair(g_Uh, g_Ul, (size_t)row * K2_ + D_ + col,
                           a0 - m1.x - m2.x, a1 - m1.y - m2.y);
            }
}

// ---------------------------------------------------------------------------
// Karatsuba M3 + closer, V half.  grid(4, 64)
// V-M3 = Zs x Es -> Vt (TRANSPOSED scatter)
// ---------------------------------------------------------------------------
__global__ void __launch_bounds__(NTHREADS) k_gemm_M3V() {
    float acc[4][4][4] = {};
    const int bn = blockIdx.x * 256;
    const int bm = blockIdx.y * 128;
    gemm_mainloop(g_Zsh + (size_t)bm * D_, g_Zsl + (size_t)bm * D_, D_,
                  g_Evsh + (size_t)bn * D_, g_Evsl + (size_t)bn * D_, D_, D_, acc);
    const int lane = threadIdx.x & 31, wid = threadIdx.x >> 5;
    const int m0 = bm + (wid >> 3) * 64, n0 = bn + (wid & 7) * 32;
    const int g = lane >> 2, tig = lane & 3;
    #pragma unroll
    for (int mt = 0; mt < 4; mt++)
        #pragma unroll
        for (int nt = 0; nt < 4; nt++)
            #pragma unroll
            for (int h = 0; h < 2; h++) {
                int row = m0 + mt * 16 + g + h * 8;
                int col = n0 + nt * 8 + tig * 2;
                int bb = row >> 11, t = row & 2047;
                float2 m1 = *(const float2*)(g_M1v + (size_t)row * D_ + col);
                float2 m2 = *(const float2*)(g_M2v + (size_t)row * D_ + col);
                float a0 = acc[mt][nt][2 * h], a1 = acc[mt][nt][2 * h + 1];
                float re0 = m1.x - m2.x,      re1 = m1.y - m2.y;
                float im0 = a0 - m1.x - m2.x, im1 = a1 - m1.y - m2.y;
                size_t base = (size_t)bb * K2_ * S_ + t;
                __nv_bfloat16 hh, ll;
                split_bf16(re0, hh, ll);
                g_Vth[base + (size_t)col * S_] = hh;       g_Vtl[base + (size_t)col * S_] = ll;
                split_bf16(re1, hh, ll);
                g_Vth[base + (size_t)(col + 1) * S_] = hh; g_Vtl[base + (size_t)(col + 1) * S_] = ll;
                split_bf16(im0, hh, ll);
                g_Vth[base + (size_t)(col + D_) * S_] = hh;     g_Vtl[base + (size_t)(col + D_) * S_] = ll;
                split_bf16(im1, hh, ll);
                g_Vth[base + (size_t)(col + D_ + 1) * S_] = hh; g_Vtl[base + (size_t)(col + D_ + 1) * S_] = ll;
            }
}

// ---------------------------------------------------------------------------
// GEMM scores: scores = Z~ @ U^T, causal tile skip   grid(8,16,4)
// ---------------------------------------------------------------------------
__global__ void __launch_bounds__(NTHREADS) k_gemm_scores() {
    if ((int)blockIdx.x * 2 > (int)blockIdx.y) return;
    float acc[4][4][4] = {};
    const int b = blockIdx.z, bm = blockIdx.y * 128, bn = blockIdx.x * 256;
    gemm_mainloop(g_Xh + ((size_t)(b * S_ + bm)) * K2_,
                  g_Xl + ((size_t)(b * S_ + bm)) * K2_, K2_,
                  g_Uh + ((size_t)(b * S_ + bn)) * K2_,
                  g_Ul + ((size_t)(b * S_ + bn)) * K2_, K2_, K2_, acc);
    const int lane = threadIdx.x & 31, wid = threadIdx.x >> 5;
    const int m0 = bm + (wid >> 3) * 64, n0 = bn + (wid & 7) * 32;
    const int g = lane >> 2, tig = lane & 3;
    float* C = g_P + (size_t)b * S_ * S_;
    #pragma unroll
    for (int mt = 0; mt < 4; mt++)
        #pragma unroll
        for (int nt = 0; nt < 4; nt++)
            #pragma unroll
            for (int h = 0; h < 2; h++) {
                int row = m0 + mt * 16 + g + h * 8;
                int col = n0 + nt * 8 + tig * 2;
                *(float2*)(C + (size_t)row * S_ + col) =
                    make_float2(acc[mt][nt][2 * h], acc[mt][nt][2 * h + 1]);
            }
}

// ---------------------------------------------------------------------------
// Causal softmax: g_P -> g_Ph/g_Pl (bf16 hi/lo, zero-padded to 128 boundary)
// ---------------------------------------------------------------------------
__global__ void __launch_bounds__(256) softmax_k() {
    const int b = blockIdx.y, s = blockIdx.x;
    const float* row = g_P + ((size_t)(b * S_ + s)) * S_;
    __nv_bfloat16* oh = g_Ph + ((size_t)(b * S_ + s)) * S_;
    __nv_bfloat16* ol = g_Pl + ((size_t)(b * S_ + s)) * S_;
    const int n = s + 1;
    const int lim = ((s >> 7) + 1) << 7;
    const float scale = 0.03125f;
    __shared__ float red[256];
    const int tid = threadIdx.x;

    float ev[8];
    float m = -3.0e38f;
    #pragma unroll
    for (int it = 0; it < 8; it++) {
        int i = tid + it * 256;
        float v = (i < n) ? row[i] : -3.0e38f;
        ev[it] = v;
        m = fmaxf(m, v);
    }
    red[tid] = m; __syncthreads();
    for (int off = 128; off > 0; off >>= 1) {
        if (tid < off) red[tid] = fmaxf(red[tid], red[tid + off]);
        __syncthreads();
    }
    const float mv = red[0] * scale;
    __syncthreads();

    float sum = 0.f;
    #pragma unroll
    for (int it = 0; it < 8; it++) {
        int i = tid + it * 256;
        float e = (i < n) ? __expf(ev[it] * scale - mv) : 0.f;
        ev[it] = e;
        sum += e;
    }
    red[tid] = sum; __syncthreads();
    for (int off = 128; off > 0; off >>= 1) {
        if (tid < off) red[tid] += red[tid + off];
        __syncthreads();
    }
    const float inv = 1.0f / red[0];

    #pragma unroll
    for (int it = 0; it < 8; it++) {
        int i = tid + it * 256;
        if (i < lim) {
            float p = (i < n) ? ev[it] * inv : 0.f;
            __nv_bfloat16 h, l;
            split_bf16(p, h, l);
            oh[i] = h; ol[i] = l;
        }
    }
}

// ---------------------------------------------------------------------------
// GEMM PV: Out = P @ Vt^T (causal K-limit), heavy tiles first  grid(8,16,4)
// ---------------------------------------------------------------------------
__global__ void __launch_bounds__(NTHREADS) k_gemm_pv(float* __restrict__ out) {
    float acc[4][4][4] = {};
    const int b = blockIdx.z;
    const int bm = (15 - (int)blockIdx.y) * 128;   // heavy-first
    const int bn = blockIdx.x * 256;
    gemm_mainloop(g_Ph + ((size_t)(b * S_ + bm)) * S_,
                  g_Pl + ((size_t)(b * S_ + bm)) * S_, S_,
                  g_Vth + ((size_t)b * K2_ + bn) * S_,
                  g_Vtl + ((size_t)b * K2_ + bn) * S_, S_,
                  bm + 128, acc);
    const int lane = threadIdx.x & 31, wid = threadIdx.x >> 5;
    const int m0 = bm + (wid >> 3) * 64, n0 = bn + (wid & 7) * 32;
    const int g = lane >> 2, tig = lane & 3;
    #pragma unroll
    for (int mt = 0; mt < 4; mt++)
        #pragma unroll
        for (int nt = 0; nt < 4; nt++)
            #pragma unroll
            for (int h = 0; h < 2; h++) {
                int s = m0 + mt * 16 + g + h * 8;
                int col = n0 + nt * 8 + tig * 2;
                int plane = col >> 10, d = col & 1023;
                *(float2*)(out + (((size_t)plane * B_ + b) * S_ + s) * (size_t)D_ + d) =
                    make_float2(acc[mt][nt][2 * h], acc[mt][nt][2 * h + 1]);
            }
}

// ---------------------------------------------------------------------------
// Launch (dual-stream capture: s2 carries pack_misc and M3V)
// ---------------------------------------------------------------------------
extern "C" void kernel_launch(void* const* d_in, const int* in_sizes, int n_in,
                              void* d_out, int out_size) {
    const float* z_real = (const float*)d_in[0];
    const float* z_imag = (const float*)d_in[1];
    const float* wq_r   = (const float*)d_in[2];
    const float* wq_i   = (const float*)d_in[3];
    const float* wk_r   = (const float*)d_in[4];
    const float* wk_i   = (const float*)d_in[5];
    const float* wv_r   = (const float*)d_in[6];
    const float* wv_i   = (const float*)d_in[7];
    float* out = (float*)d_out;

    static int init_done = 0;
    static cudaStream_t s2;
    static cudaEvent_t e0, eA, eM, eV;
    if (!init_done) {
        cudaFuncSetAttribute(k_gemm_G,      cudaFuncAttributeMaxDynamicSharedMemorySize, SMEM_G);
        cudaFuncSetAttribute(k_gemm_M12,    cudaFuncAttributeMaxDynamicSharedMemorySize, SMEM_G);
        cudaFuncSetAttribute(k_gemm_M3U,    cudaFuncAttributeMaxDynamicSharedMemorySize, SMEM_G);
        cudaFuncSetAttribute(k_gemm_M3V,    cudaFuncAttributeMaxDynamicSharedMemorySize, SMEM_G);
        cudaFuncSetAttribute(k_gemm_scores, cudaFuncAttributeMaxDynamicSharedMemorySize, SMEM_G);
        cudaFuncSetAttribute(k_gemm_pv,     cudaFuncAttributeMaxDynamicSharedMemorySize, SMEM_G);
        cudaStreamCreateWithFlags(&s2, cudaStreamNonBlocking);
        cudaEventCreateWithFlags(&e0, cudaEventDisableTiming);
        cudaEventCreateWithFlags(&eA, cudaEventDisableTiming);
        cudaEventCreateWithFlags(&eM, cudaEventDisableTiming);
        cudaEventCreateWithFlags(&eV, cudaEventDisableTiming);
        init_done = 1;
    }

    // Fork s2 from the origin stream.
    cudaEventRecord(e0, 0);
    cudaStreamWaitEvent(s2, e0, 0);

    // s2: X/Zs/Ev packing (independent of G chain).
    pack_misc<<<36864, 256, 0, s2>>>(z_real, z_imag, wv_r, wv_i);
    cudaEventRecord(eA, s2);

    // s0: W^T packing -> G -> reduce (needs only pack_wT).
    pack_wT<<<dim3(64, 64, 2), dim3(32, 8)>>>(wq_r, wq_i, wk_r, wk_i);
    k_gemm_G<<<dim3(D_ / 256, K2_ / 128, 2), NTHREADS, SMEM_G>>>();
    reduce_G<<<(D_ * D_) / 256, 256>>>();

    // s0: M12 needs X (eA) + G.
    cudaStreamWaitEvent(0, eA, 0);
    k_gemm_M12<<<dim3(16, M_ / 128), NTHREADS, SMEM_G>>>();
    cudaEventRecord(eM, 0);

    // s0: U closer -> scores -> softmax.
    k_gemm_M3U<<<dim3(4, M_ / 128), NTHREADS, SMEM_G>>>();
    // s2: V closer overlaps scores.
    cudaStreamWaitEvent(s2, eM, 0);
    k_gemm_M3V<<<dim3(4, M_ / 128), NTHREADS, SMEM_G, s2>>>();
    cudaEventRecord(eV, s2);

    k_gemm_scores<<<dim3(S_ / 256, S_ / 128, B_), NTHREADS, SMEM_G>>>();
    softmax_k<<<dim3(S_, B_), 256>>>();

    // s0: PV needs softmax (in-stream) + Vt (eV).
    cudaStreamWaitEvent(0, eV, 0);
    k_gemm_pv<<<dim3(K2_ / 256, S_ / 128, B_), NTHREADS, SMEM_G>>>(out);
}